// round 8
// baseline (speedup 1.0000x reference)
#include <cuda_runtime.h>
#include <cstring>

// B-spline layer via per-span cubic collapse:
//   u = 61*x, m = floor(u), t = u-m
//   out[b,f] = A0(m,f) + A1 t + A2 t^2 + A3 t^3
// A_c(m,f) = sum_r basis[m][r][c] * cp[m+r][f], bias folded into A0.
// Basis polys are input-independent -> built on host (double precision),
// passed as a 3904-byte kernel parameter (constant bank, warp-uniform).
//
// R8 structure (latency-oriented):
//  - feature-split: each CTA owns a 64-feature half; smem table 61x64 float4
//    = 62.5 KB -> 2-3 CTAs/SM co-resident (fold of one overlaps eval of other)
//  - all 16 x LDGs issued at kernel entry (MLP=16); the fold phase + barrier
//    hide the DRAM round trip, eval reads registers.

#define NF    128
#define FH    64            // features per CTA
#define NSPAN 61
#define TB    512
#define RPB   128           // rows per block
#define RPT   16            // rows per thread (RPB / 8 lrows)
#define UC    4             // rows per eval chunk

#define SMEM_BYTES (NSPAN * FH * 16)

struct BasisTab {
    float4 b[NSPAN * 4];    // [m][r] -> (c0,c1,c2,c3) coeffs in t
};

template <bool GUARD>
__global__ void __launch_bounds__(TB, 2)
bspline_kernel(const BasisTab bt,
               const float* __restrict__ x,
               const float* __restrict__ cp,
               const float* __restrict__ bias,
               float* __restrict__ out,
               int B)
{
    extern __shared__ float4 table[];   // [61*64]

    const int tid   = threadIdx.x;
    const int fhalf = blockIdx.x & 1;           // which 64-feature half
    const int tile  = blockIdx.x >> 1;          // row tile
    const int fl    = tid & (FH - 1);           // local feature 0..63
    const int lrow  = tid >> 6;                 // 0..7
    const int fg    = fhalf * FH + fl;          // global feature

    const int rowBase = tile * RPB + lrow;

    // ---- stage A: front-load ALL x values (MLP = 16); fold hides latency ----
    float xv[RPT];
#pragma unroll
    for (int j = 0; j < RPT; j++) {
        const int row = rowBase + j * 8;
        if (!GUARD || row < B) xv[j] = x[row * NF + fg];
    }

    // ---- stage B: fold cp + bias -> per-span cubic table (this half) ----
    // idx = m*64 + fl' ; warp-uniform m -> bt reads are constant-bank
    // broadcasts; cp reads coalesced across f.
#pragma unroll
    for (int it = 0; it < (NSPAN * FH + TB - 1) / TB; it++) {
        const int idx = tid + it * TB;
        if (idx < NSPAN * FH) {
            const int m  = idx >> 6;
            const int ff = fhalf * FH + (idx & (FH - 1));
            const float c0 = cp[(m + 0) * NF + ff];
            const float c1 = cp[(m + 1) * NF + ff];
            const float c2 = cp[(m + 2) * NF + ff];
            const float c3 = cp[(m + 3) * NF + ff];
            const float4 b0 = bt.b[m * 4 + 0];
            const float4 b1 = bt.b[m * 4 + 1];
            const float4 b2 = bt.b[m * 4 + 2];
            const float4 b3 = bt.b[m * 4 + 3];
            float4 A;
            A.x = fmaf(c0, b0.x, fmaf(c1, b1.x, fmaf(c2, b2.x, fmaf(c3, b3.x, bias[ff]))));
            A.y = fmaf(c0, b0.y, fmaf(c1, b1.y, fmaf(c2, b2.y, c3 * b3.y)));
            A.z = fmaf(c0, b0.z, fmaf(c1, b1.z, fmaf(c2, b2.z, c3 * b3.z)));
            A.w = fmaf(c0, b0.w, fmaf(c1, b1.w, fmaf(c2, b2.w, c3 * b3.w)));
            table[idx] = A;
        }
    }
    __syncthreads();

    // ---- stage C: eval from registers + smem (LDS.128 conflict-free) ----
#pragma unroll
    for (int chunk = 0; chunk < RPT / UC; chunk++) {
        float  t[UC];
        float4 A[UC];
#pragma unroll
        for (int jj = 0; jj < UC; jj++) {
            const int j = chunk * UC + jj;
            const float u  = xv[j] * 61.0f;
            const float fm = floorf(u);          // x in [0,1) -> m in [0,60]
            t[jj] = u - fm;
            A[jj] = table[(int)fm * FH + fl];
        }
#pragma unroll
        for (int jj = 0; jj < UC; jj++) {
            const int j = chunk * UC + jj;
            float r = fmaf(A[jj].w, t[jj], A[jj].z);
            r = fmaf(r, t[jj], A[jj].y);
            r = fmaf(r, t[jj], A[jj].x);
            const int row = rowBase + j * 8;
            if (!GUARD || row < B) out[row * NF + fg] = r;
        }
    }
}

// ---- host-side basis polynomial construction (input-independent) ----
static inline double knotd(int im3) {
    double v = (double)im3;
    if (v < 0.0) v = 0.0;
    if (v > 61.0) v = 61.0;
    return v;
}

static void build_basis(BasisTab* bt)
{
    for (int m = 0; m < NSPAN; m++) {
        double P[4][4];
        memset(P, 0, sizeof(P));
        P[0][0] = 1.0;   // k=0: N_{m+3}^0 = 1 on the span

        for (int k = 1; k <= 3; k++) {
            double Q[4][4];
            memset(Q, 0, sizeof(Q));
            for (int j = 0; j <= k; j++) {
                const int i = m + 3 - k + j;
                const double ti   = knotd(i - 3);
                const double ti1  = knotd(i - 2);
                const double tik  = knotd(i - 3 + k);
                const double tik1 = knotd(i - 2 + k);
                if (j >= 1 && tik != ti) {
                    const double inv = 1.0 / (tik - ti);
                    const double a0  = ((double)m - ti) * inv;
                    for (int c = 0; c < 4; c++) Q[j][c]     += a0  * P[j - 1][c];
                    for (int c = 0; c < 3; c++) Q[j][c + 1] += inv * P[j - 1][c];
                }
                if (j <= k - 1 && tik1 != ti1) {
                    const double inv = 1.0 / (tik1 - ti1);
                    const double b0  = (tik1 - (double)m) * inv;
                    for (int c = 0; c < 4; c++) Q[j][c]     += b0  * P[j][c];
                    for (int c = 0; c < 3; c++) Q[j][c + 1] -= inv * P[j][c];
                }
            }
            memcpy(P, Q, sizeof(P));
        }
        for (int r = 0; r < 4; r++) {
            bt->b[m * 4 + r].x = (float)P[r][0];
            bt->b[m * 4 + r].y = (float)P[r][1];
            bt->b[m * 4 + r].z = (float)P[r][2];
            bt->b[m * 4 + r].w = (float)P[r][3];
        }
    }
}

extern "C" void kernel_launch(void* const* d_in, const int* in_sizes, int n_in,
                              void* d_out, int out_size)
{
    const float* x    = (const float*)d_in[0];
    const float* cp   = (const float*)d_in[1];
    const float* bias = (const float*)d_in[2];
    float* out = (float*)d_out;

    const int B = in_sizes[0] / NF;   // 16384 rows

    static BasisTab bt;
    build_basis(&bt);                 // deterministic per call

    static bool attrSet = false;
    if (!attrSet) {
        cudaFuncSetAttribute(bspline_kernel<false>,
                             cudaFuncAttributeMaxDynamicSharedMemorySize, SMEM_BYTES);
        cudaFuncSetAttribute(bspline_kernel<true>,
                             cudaFuncAttributeMaxDynamicSharedMemorySize, SMEM_BYTES);
        attrSet = true;
    }

    if ((B % RPB) == 0) {
        const int grid = (B / RPB) * 2;                 // 256 CTAs
        bspline_kernel<false><<<grid, TB, SMEM_BYTES>>>(bt, x, cp, bias, out, B);
    } else {
        const int grid = ((B + RPB - 1) / RPB) * 2;
        bspline_kernel<true><<<grid, TB, SMEM_BYTES>>>(bt, x, cp, bias, out, B);
    }
}